// round 9
// baseline (speedup 1.0000x reference)
#include <cuda_runtime.h>
#include <cstdint>

// Problem constants
#define NPTS 200000
#define NCLS 20
#define NPROP 256
#define NPAIR 400000
#define THRESH 100

// Derived
#define WPP (NPTS / 32)                 // 6250 words per proposal
#define WORDS ((size_t)NPROP * WPP)     // 1,600,000 words

// Output layout (float32, concatenated in return order)
#define OFF_SCORES  ((size_t)0)
#define OFF_MASKS   ((size_t)256)
#define OFF_CLASSES ((size_t)(256 + (size_t)NPROP * NPTS))
#define OFF_BIAS    (OFF_CLASSES + 256)
#define OFF_PROBS   (OFF_BIAS + (size_t)NPTS * 3)

#define PAD 32   // 128B stride between per-proposal counters

// Scratch (device globals: allocation-free)
__device__ unsigned int g_bits[WORDS];          // 6.4 MB dedupe bitmask
__device__ unsigned char g_first[NPAIR];        // per-pair first-setter verdict
__device__ int   g_rep_p[NPROP * PAD];
__device__ int   g_count_p[NPROP * PAD];
__device__ float g_score_p[NPROP * PAD];
__device__ int   g_segpred[NPTS];

// Fast exp on FMA pipe (no MUFU). rel err ~2e-6.
__device__ __forceinline__ float fexp(float x) {
    const float MAGIC = 12582912.0f;           // 1.5 * 2^23
    float t = fmaf(x, 1.4426950408889634f, MAGIC);
    int   n = __float_as_int(t) - 0x4B400000;
    float f = fmaf(x, 1.4426950408889634f, -(t - MAGIC));
    float p = 1.3333558146e-3f;
    p = fmaf(p, f, 9.6181291076e-3f);
    p = fmaf(p, f, 5.5504108664e-2f);
    p = fmaf(p, f, 2.4022650696e-1f);
    p = fmaf(p, f, 6.9314718056e-1f);
    p = fmaf(p, f, 1.0f);
    return __int_as_float(__float_as_int(p) + (n << 23));
}

// --- s0: dedupe scatter (only dep: zeroed bitmask). Records verdicts. ---
__global__ void __launch_bounds__(1024)
k_scatter_lite(const int* __restrict__ pid, const int* __restrict__ nid) {
    int m = blockIdx.x * blockDim.x + threadIdx.x;
    if (m >= NPAIR) return;
    size_t bit = (size_t)pid[m] * NPTS + nid[m];
    unsigned int msk = 1u << (bit & 31u);
    unsigned int old = atomicOr(&g_bits[bit >> 5], msk);
    g_first[m] = (old & msk) ? 0 : 1;
}

// --- s0: counts via popc over the final bitmask (6.4 MB read) ---
// Each block covers 256 consecutive words -> spans at most 2 proposals.
__global__ void k_count() {
    __shared__ int s_cnt[2];
    int tid = threadIdx.x;
    if (tid < 2) s_cnt[tid] = 0;
    __syncthreads();
    int t = blockIdx.x * 256 + tid;
    int pbase = (blockIdx.x * 256) / WPP;
    int p = t / WPP;
    unsigned int w = g_bits[t];
    if (w) atomicAdd(&s_cnt[p - pbase], __popc(w));
    __syncthreads();
    if (tid < 2) {
        int pp = pbase + tid;
        if (pp < NPROP && s_cnt[tid]) atomicAdd(&g_count_p[pp * PAD], s_cnt[tid]);
    }
}

// --- s0: mask expansion only (warp-coalesced 512B stores) ---
__global__ void k_masks(float* __restrict__ out_masks) {
    int tid = threadIdx.x;
    int t = blockIdx.x * blockDim.x + tid;   // word index (exact grid)
    int lane = tid & 31;
    int p = t / WPP;
    unsigned int w = g_bits[t];
    if (g_count_p[p * PAD] <= THRESH) w = 0u;

    size_t warp_word0 = (size_t)(t - lane);
    float4* dst = (float4*)out_masks + warp_word0 * 8;   // 8 float4 per word
    int nib = (lane & 7) * 4;
#pragma unroll
    for (int i = 0; i < 8; i++) {
        unsigned int src = __shfl_sync(0xFFFFFFFFu, w, i * 4 + (lane >> 3));
        float4 f;
        f.x = (float)((src >> (nib + 0)) & 1u);
        f.y = (float)((src >> (nib + 1)) & 1u);
        f.z = (float)((src >> (nib + 2)) & 1u);
        f.w = (float)((src >> (nib + 3)) & 1u);
        dst[(size_t)i * 32 + lane] = f;
    }
}

// --- sB: staged softmax + argmax (padded smem rows, FMA exp) ---
__global__ void k_softmax(const float* __restrict__ logit,
                          float* __restrict__ probs_out) {
    __shared__ float s[256 * 21];   // 21 KB
    int tid  = threadIdx.x;
    int base = blockIdx.x * 256;
    int count = NPTS - base;
    if (count > 256) count = 256;
    int tot = count * NCLS;

    const float* src = logit + (size_t)base * NCLS;
    for (int i = tid; i < tot; i += 256) {
        int row = i / NCLS, col = i - row * NCLS;
        s[row * 21 + col] = src[i];
    }
    __syncthreads();

    if (tid < count) {
        float* row = s + tid * 21;
        float v[NCLS];
#pragma unroll
        for (int i = 0; i < NCLS; i++) v[i] = row[i];
        float m = v[0]; int am = 0;
#pragma unroll
        for (int i = 1; i < NCLS; i++) if (v[i] > m) { m = v[i]; am = i; }
        float e[NCLS]; float sum = 0.0f;
#pragma unroll
        for (int i = 0; i < NCLS; i++) { e[i] = fexp(v[i] - m); sum += e[i]; }
        float inv = 1.0f / sum;
#pragma unroll
        for (int i = 0; i < NCLS; i++) row[i] = e[i] * inv;
        g_segpred[base + tid] = am;
    }
    __syncthreads();

    float* dst = probs_out + (size_t)base * NCLS;
    for (int i = tid; i < tot; i += 256) {
        int row = i / NCLS, col = i - row * NCLS;
        dst[i] = s[row * 21 + col];
    }
}

// --- sC: segment_min via smem privatization (g_rep_p pre-memset 0x7F) ---
__global__ void k_segmin(const int* __restrict__ pid, const int* __restrict__ nid) {
    __shared__ int sm[NPROP];
    int tid = threadIdx.x;
    for (int i = tid; i < NPROP; i += blockDim.x) sm[i] = 0x7FFFFFFF;
    __syncthreads();
    int stride = gridDim.x * blockDim.x;
    for (int m = blockIdx.x * blockDim.x + tid; m < NPAIR; m += stride)
        atomicMin(&sm[pid[m]], nid[m]);
    __syncthreads();
    for (int i = tid; i < NPROP; i += blockDim.x)
        if (sm[i] != 0x7FFFFFFF) atomicMin(&g_rep_p[i * PAD], sm[i]);
}

// --- sB: score gather for unique pairs only (runs under k_masks) ---
__global__ void __launch_bounds__(1024, 2)
k_gather(const int* __restrict__ pid, const int* __restrict__ nid,
         const float* __restrict__ probs) {
    __shared__ int   s_inst[NPROP];
    __shared__ float s_scr[NPROP];
    int tid = threadIdx.x;
    if (tid < NPROP) {
        int r = g_rep_p[tid * PAD];
        if (r > NPTS - 1) r = NPTS - 1;
        s_inst[tid] = g_segpred[r];
        s_scr[tid] = 0.0f;
    }
    __syncthreads();

    int stride = gridDim.x * blockDim.x;
    for (int m = blockIdx.x * blockDim.x + tid; m < NPAIR; m += stride) {
        if (g_first[m]) {
            int p = pid[m];
            int n = nid[m];
            atomicAdd(&s_scr[p], __ldg(&probs[(size_t)n * NCLS + s_inst[p]]));
        }
    }
    __syncthreads();
    if (tid < NPROP && s_scr[tid] != 0.0f)
        atomicAdd(&g_score_p[tid * PAD], s_scr[tid]);
}

// --- sB tail: scores + classes (tiny) ---
__global__ void k_finalize(float* __restrict__ out_scores,
                           float* __restrict__ out_classes) {
    int p = threadIdx.x;
    int c = g_count_p[p * PAD];
    int flag = (c > THRESH) ? 1 : 0;
    int cm = c > 1 ? c : 1;
    int r = g_rep_p[p * PAD];
    if (r > NPTS - 1) r = NPTS - 1;
    int inst = g_segpred[r];
    out_scores[p]  = flag ? (g_score_p[p * PAD] / (float)cm) : 0.0f;
    out_classes[p] = flag ? (float)inst : -1.0f;
}

// --- sD: bias passthrough (independent) ---
__global__ void k_bias(const float* __restrict__ bias, float* __restrict__ bias_out) {
    int t = blockIdx.x * blockDim.x + threadIdx.x;
    if (t < NPTS * 3 / 4) ((float4*)bias_out)[t] = ((const float4*)bias)[t];
}

extern "C" void kernel_launch(void* const* d_in, const int* in_sizes, int n_in,
                              void* d_out, int out_size) {
    const float* logit = (const float*)d_in[0];
    const float* bias  = (const float*)d_in[1];
    // d_in[2] = coord: dead
    const int* pid = (const int*)d_in[3];
    const int* nid = (const int*)d_in[4];

    float* out = (float*)d_out;
    float* out_scores  = out + OFF_SCORES;
    float* out_masks   = out + OFF_MASKS;
    float* out_classes = out + OFF_CLASSES;
    float* out_bias    = out + OFF_BIAS;
    float* out_probs   = out + OFF_PROBS;

    static cudaStream_t sB = nullptr, sC = nullptr, sD = nullptr;
    static cudaEvent_t eRoot, eS, eC, eCnt, eB, eD;
    static void *a_bits = nullptr, *a_rep = nullptr, *a_cnt = nullptr, *a_scr = nullptr;
    if (!sB) {
        cudaStreamCreateWithFlags(&sB, cudaStreamNonBlocking);
        cudaStreamCreateWithFlags(&sC, cudaStreamNonBlocking);
        cudaStreamCreateWithFlags(&sD, cudaStreamNonBlocking);
        cudaEventCreateWithFlags(&eRoot, cudaEventDisableTiming);
        cudaEventCreateWithFlags(&eS,   cudaEventDisableTiming);
        cudaEventCreateWithFlags(&eC,   cudaEventDisableTiming);
        cudaEventCreateWithFlags(&eCnt, cudaEventDisableTiming);
        cudaEventCreateWithFlags(&eB,   cudaEventDisableTiming);
        cudaEventCreateWithFlags(&eD,   cudaEventDisableTiming);
        cudaGetSymbolAddress(&a_bits, g_bits);
        cudaGetSymbolAddress(&a_rep,  g_rep_p);
        cudaGetSymbolAddress(&a_cnt,  g_count_p);
        cudaGetSymbolAddress(&a_scr,  g_score_p);
    }

    // fork
    cudaEventRecord(eRoot, 0);
    cudaStreamWaitEvent(sB, eRoot, 0);
    cudaStreamWaitEvent(sC, eRoot, 0);
    cudaStreamWaitEvent(sD, eRoot, 0);

    // s0 (critical path): zero bits+counts -> scatter -> count -> masks
    cudaMemsetAsync(a_bits, 0, WORDS * 4, 0);
    cudaMemsetAsync(a_cnt, 0, NPROP * PAD * 4, 0);
    k_scatter_lite<<<(NPAIR + 1023) / 1024, 1024>>>(pid, nid);
    cudaEventRecord(eS, 0);
    k_count<<<(int)(WORDS / 256), 256>>>();
    cudaEventRecord(eCnt, 0);
    k_masks<<<(int)(WORDS / 256), 256>>>(out_masks);

    // sC: memset rep/score -> segmin
    cudaMemsetAsync(a_rep, 0x7F, NPROP * PAD * 4, sC);   // 0x7F7F7F7F > NPTS
    cudaMemsetAsync(a_scr, 0, NPROP * PAD * 4, sC);
    k_segmin<<<148, 512, 0, sC>>>(pid, nid);
    cudaEventRecord(eC, sC);

    // sB: softmax -> (wait scatter+segmin) gather -> (wait count) finalize
    k_softmax<<<(NPTS + 255) / 256, 256, 0, sB>>>(logit, out_probs);
    cudaStreamWaitEvent(sB, eS, 0);
    cudaStreamWaitEvent(sB, eC, 0);
    k_gather<<<296, 1024, 0, sB>>>(pid, nid, out_probs);
    cudaStreamWaitEvent(sB, eCnt, 0);
    k_finalize<<<1, NPROP, 0, sB>>>(out_scores, out_classes);
    cudaEventRecord(eB, sB);

    // sD: bias passthrough
    k_bias<<<(NPTS * 3 / 4 + 255) / 256, 256, 0, sD>>>(bias, out_bias);
    cudaEventRecord(eD, sD);

    // join everything into stream 0
    cudaStreamWaitEvent(0, eB, 0);
    cudaStreamWaitEvent(0, eD, 0);
}

// round 10
// speedup vs baseline: 1.0150x; 1.0150x over previous
#include <cuda_runtime.h>
#include <cstdint>

// Problem constants
#define NPTS 200000
#define NCLS 20
#define NPROP 256
#define NPAIR 400000
#define THRESH 100

// Derived
#define WPP (NPTS / 32)                 // 6250 words per proposal
#define WORDS ((size_t)NPROP * WPP)     // 1,600,000 words

// Output layout (float32, concatenated in return order)
#define OFF_SCORES  ((size_t)0)
#define OFF_MASKS   ((size_t)256)
#define OFF_CLASSES ((size_t)(256 + (size_t)NPROP * NPTS))
#define OFF_BIAS    (OFF_CLASSES + 256)
#define OFF_PROBS   (OFF_BIAS + (size_t)NPTS * 3)

#define PAD 32   // 128B stride between per-proposal counters

// Scratch (device globals: allocation-free)
__device__ unsigned int g_bits[WORDS];          // 6.4 MB dedupe bitmask
__device__ unsigned char g_first[NPAIR];        // per-pair first-setter verdict
__device__ int   g_rep_p[NPROP * PAD];
__device__ int   g_count_p[NPROP * PAD];
__device__ float g_score_p[NPROP * PAD];
__device__ int   g_segpred[NPTS];

// Fast exp on FMA pipe (no MUFU). rel err ~2e-6.
__device__ __forceinline__ float fexp(float x) {
    const float MAGIC = 12582912.0f;           // 1.5 * 2^23
    float t = fmaf(x, 1.4426950408889634f, MAGIC);
    int   n = __float_as_int(t) - 0x4B400000;
    float f = fmaf(x, 1.4426950408889634f, -(t - MAGIC));
    float p = 1.3333558146e-3f;
    p = fmaf(p, f, 9.6181291076e-3f);
    p = fmaf(p, f, 5.5504108664e-2f);
    p = fmaf(p, f, 2.4022650696e-1f);
    p = fmaf(p, f, 6.9314718056e-1f);
    p = fmaf(p, f, 1.0f);
    return __int_as_float(__float_as_int(p) + (n << 23));
}

// --- sH: fused pair pass: dedupe atomicOr + verdict + smem segment-min ---
__global__ void __launch_bounds__(1024, 2)
k_pairs(const int* __restrict__ pid, const int* __restrict__ nid) {
    __shared__ int sm[NPROP];
    int tid = threadIdx.x;
    if (tid < NPROP) sm[tid] = 0x7FFFFFFF;
    __syncthreads();

    int stride = gridDim.x * blockDim.x;
    for (int m = blockIdx.x * blockDim.x + tid; m < NPAIR; m += stride) {
        int p = pid[m];
        int n = nid[m];
        atomicMin(&sm[p], n);
        size_t bit = (size_t)p * NPTS + n;
        unsigned int msk = 1u << (bit & 31u);
        unsigned int old = atomicOr(&g_bits[bit >> 5], msk);
        g_first[m] = (old & msk) ? 0 : 1;
    }
    __syncthreads();
    if (tid < NPROP && sm[tid] != 0x7FFFFFFF)
        atomicMin(&g_rep_p[tid * PAD], sm[tid]);
}

// --- sH: counts via popc over the final bitmask (6.4 MB read) ---
// Each block covers 256 consecutive words -> spans at most 2 proposals.
__global__ void k_count() {
    __shared__ int s_cnt[2];
    int tid = threadIdx.x;
    if (tid < 2) s_cnt[tid] = 0;
    __syncthreads();
    int t = blockIdx.x * 256 + tid;
    int pbase = (blockIdx.x * 256) / WPP;
    int p = t / WPP;
    unsigned int w = g_bits[t];
    if (w) atomicAdd(&s_cnt[p - pbase], __popc(w));
    __syncthreads();
    if (tid < 2) {
        int pp = pbase + tid;
        if (pp < NPROP && s_cnt[tid]) atomicAdd(&g_count_p[pp * PAD], s_cnt[tid]);
    }
}

// --- sH: mask expansion (warp-coalesced 512B stores) ---
__global__ void k_masks(float* __restrict__ out_masks) {
    int tid = threadIdx.x;
    int t = blockIdx.x * blockDim.x + tid;   // word index (exact grid)
    int lane = tid & 31;
    int p = t / WPP;
    unsigned int w = g_bits[t];
    if (g_count_p[p * PAD] <= THRESH) w = 0u;

    size_t warp_word0 = (size_t)(t - lane);
    float4* dst = (float4*)out_masks + warp_word0 * 8;   // 8 float4 per word
    int nib = (lane & 7) * 4;
#pragma unroll
    for (int i = 0; i < 8; i++) {
        unsigned int src = __shfl_sync(0xFFFFFFFFu, w, i * 4 + (lane >> 3));
        float4 f;
        f.x = (float)((src >> (nib + 0)) & 1u);
        f.y = (float)((src >> (nib + 1)) & 1u);
        f.z = (float)((src >> (nib + 2)) & 1u);
        f.w = (float)((src >> (nib + 3)) & 1u);
        dst[(size_t)i * 32 + lane] = f;
    }
}

// --- sB: staged softmax + argmax (padded smem rows, FMA exp) ---
__global__ void k_softmax(const float* __restrict__ logit,
                          float* __restrict__ probs_out) {
    __shared__ float s[256 * 21];   // 21 KB
    int tid  = threadIdx.x;
    int base = blockIdx.x * 256;
    int count = NPTS - base;
    if (count > 256) count = 256;
    int tot = count * NCLS;

    const float* src = logit + (size_t)base * NCLS;
    for (int i = tid; i < tot; i += 256) {
        int row = i / NCLS, col = i - row * NCLS;
        s[row * 21 + col] = src[i];
    }
    __syncthreads();

    if (tid < count) {
        float* row = s + tid * 21;
        float v[NCLS];
#pragma unroll
        for (int i = 0; i < NCLS; i++) v[i] = row[i];
        float m = v[0]; int am = 0;
#pragma unroll
        for (int i = 1; i < NCLS; i++) if (v[i] > m) { m = v[i]; am = i; }
        float e[NCLS]; float sum = 0.0f;
#pragma unroll
        for (int i = 0; i < NCLS; i++) { e[i] = fexp(v[i] - m); sum += e[i]; }
        float inv = 1.0f / sum;
#pragma unroll
        for (int i = 0; i < NCLS; i++) row[i] = e[i] * inv;
        g_segpred[base + tid] = am;
    }
    __syncthreads();

    float* dst = probs_out + (size_t)base * NCLS;
    for (int i = tid; i < tot; i += 256) {
        int row = i / NCLS, col = i - row * NCLS;
        dst[i] = s[row * 21 + col];
    }
}

// --- sB: score gather for unique pairs only (runs under k_masks) ---
__global__ void __launch_bounds__(1024, 2)
k_gather(const int* __restrict__ pid, const int* __restrict__ nid,
         const float* __restrict__ probs) {
    __shared__ int   s_inst[NPROP];
    __shared__ float s_scr[NPROP];
    int tid = threadIdx.x;
    if (tid < NPROP) {
        int r = g_rep_p[tid * PAD];
        if (r > NPTS - 1) r = NPTS - 1;
        s_inst[tid] = g_segpred[r];
        s_scr[tid] = 0.0f;
    }
    __syncthreads();

    int stride = gridDim.x * blockDim.x;
    for (int m = blockIdx.x * blockDim.x + tid; m < NPAIR; m += stride) {
        if (g_first[m]) {
            int p = pid[m];
            int n = nid[m];
            atomicAdd(&s_scr[p], __ldg(&probs[(size_t)n * NCLS + s_inst[p]]));
        }
    }
    __syncthreads();
    if (tid < NPROP && s_scr[tid] != 0.0f)
        atomicAdd(&g_score_p[tid * PAD], s_scr[tid]);
}

// --- sB tail: scores + classes (tiny) ---
__global__ void k_finalize(float* __restrict__ out_scores,
                           float* __restrict__ out_classes) {
    int p = threadIdx.x;
    int c = g_count_p[p * PAD];
    int flag = (c > THRESH) ? 1 : 0;
    int cm = c > 1 ? c : 1;
    int r = g_rep_p[p * PAD];
    if (r > NPTS - 1) r = NPTS - 1;
    int inst = g_segpred[r];
    out_scores[p]  = flag ? (g_score_p[p * PAD] / (float)cm) : 0.0f;
    out_classes[p] = flag ? (float)inst : -1.0f;
}

// --- sD: bias passthrough (independent) ---
__global__ void k_bias(const float* __restrict__ bias, float* __restrict__ bias_out) {
    int t = blockIdx.x * blockDim.x + threadIdx.x;
    if (t < NPTS * 3 / 4) ((float4*)bias_out)[t] = ((const float4*)bias)[t];
}

extern "C" void kernel_launch(void* const* d_in, const int* in_sizes, int n_in,
                              void* d_out, int out_size) {
    const float* logit = (const float*)d_in[0];
    const float* bias  = (const float*)d_in[1];
    // d_in[2] = coord: dead
    const int* pid = (const int*)d_in[3];
    const int* nid = (const int*)d_in[4];

    float* out = (float*)d_out;
    float* out_scores  = out + OFF_SCORES;
    float* out_masks   = out + OFF_MASKS;
    float* out_classes = out + OFF_CLASSES;
    float* out_bias    = out + OFF_BIAS;
    float* out_probs   = out + OFF_PROBS;

    static cudaStream_t sH = nullptr, sB = nullptr, sD = nullptr;
    static cudaEvent_t eRoot, eP, eCnt, eH, eB, eD;
    static void *a_bits = nullptr, *a_rep = nullptr, *a_cnt = nullptr, *a_scr = nullptr;
    if (!sH) {
        int loPri, hiPri;   // hiPri is the numerically least (greatest priority)
        cudaDeviceGetStreamPriorityRange(&loPri, &hiPri);
        cudaStreamCreateWithPriority(&sH, cudaStreamNonBlocking, hiPri);
        cudaStreamCreateWithPriority(&sB, cudaStreamNonBlocking, loPri);
        cudaStreamCreateWithPriority(&sD, cudaStreamNonBlocking, loPri);
        cudaEventCreateWithFlags(&eRoot, cudaEventDisableTiming);
        cudaEventCreateWithFlags(&eP,   cudaEventDisableTiming);
        cudaEventCreateWithFlags(&eCnt, cudaEventDisableTiming);
        cudaEventCreateWithFlags(&eH,   cudaEventDisableTiming);
        cudaEventCreateWithFlags(&eB,   cudaEventDisableTiming);
        cudaEventCreateWithFlags(&eD,   cudaEventDisableTiming);
        cudaGetSymbolAddress(&a_bits, g_bits);
        cudaGetSymbolAddress(&a_rep,  g_rep_p);
        cudaGetSymbolAddress(&a_cnt,  g_count_p);
        cudaGetSymbolAddress(&a_scr,  g_score_p);
    }

    // fork from stream 0
    cudaEventRecord(eRoot, 0);
    cudaStreamWaitEvent(sH, eRoot, 0);
    cudaStreamWaitEvent(sB, eRoot, 0);
    cudaStreamWaitEvent(sD, eRoot, 0);

    // sH (critical, high priority): memsets -> pairs -> count -> masks
    cudaMemsetAsync(a_bits, 0, WORDS * 4, sH);
    cudaMemsetAsync(a_cnt, 0, NPROP * PAD * 4, sH);
    cudaMemsetAsync(a_rep, 0x7F, NPROP * PAD * 4, sH);   // 0x7F7F7F7F > NPTS
    cudaMemsetAsync(a_scr, 0, NPROP * PAD * 4, sH);
    k_pairs<<<296, 1024, 0, sH>>>(pid, nid);
    cudaEventRecord(eP, sH);
    k_count<<<(int)(WORDS / 256), 256, 0, sH>>>();
    cudaEventRecord(eCnt, sH);
    k_masks<<<(int)(WORDS / 256), 256, 0, sH>>>(out_masks);
    cudaEventRecord(eH, sH);

    // sB (low priority): softmax -> (wait pairs) gather -> (wait count) finalize
    k_softmax<<<(NPTS + 255) / 256, 256, 0, sB>>>(logit, out_probs);
    cudaStreamWaitEvent(sB, eP, 0);
    k_gather<<<296, 1024, 0, sB>>>(pid, nid, out_probs);
    cudaStreamWaitEvent(sB, eCnt, 0);
    k_finalize<<<1, NPROP, 0, sB>>>(out_scores, out_classes);
    cudaEventRecord(eB, sB);

    // sD (low priority): bias passthrough
    k_bias<<<(NPTS * 3 / 4 + 255) / 256, 256, 0, sD>>>(bias, out_bias);
    cudaEventRecord(eD, sD);

    // join everything into stream 0
    cudaStreamWaitEvent(0, eH, 0);
    cudaStreamWaitEvent(0, eB, 0);
    cudaStreamWaitEvent(0, eD, 0);
}

// round 11
// speedup vs baseline: 1.0556x; 1.0400x over previous
#include <cuda_runtime.h>
#include <cstdint>

// Problem constants
#define NPTS 200000
#define NCLS 20
#define NPROP 256
#define NPAIR 400000
#define THRESH 100

// Derived
#define WPP (NPTS / 32)                 // 6250 words per proposal
#define WORDS ((size_t)NPROP * WPP)     // 1,600,000 words

// Output layout (float32, concatenated in return order)
#define OFF_SCORES  ((size_t)0)
#define OFF_MASKS   ((size_t)256)
#define OFF_CLASSES ((size_t)(256 + (size_t)NPROP * NPTS))
#define OFF_BIAS    (OFF_CLASSES + 256)
#define OFF_PROBS   (OFF_BIAS + (size_t)NPTS * 3)

#define PAD 32   // 128B stride between per-proposal counters

// Scratch (device globals: allocation-free)
__device__ unsigned int g_bits[WORDS];          // 6.4 MB dedupe bitmask
__device__ unsigned char g_first[NPAIR];        // per-pair first-setter verdict
__device__ int   g_rep_p[NPROP * PAD];
__device__ int   g_count_p[NPROP * PAD];
__device__ float g_score_p[NPROP * PAD];
__device__ int   g_segpred[NPTS];

// Fast exp on FMA pipe (no MUFU). rel err ~2e-6.
__device__ __forceinline__ float fexp(float x) {
    const float MAGIC = 12582912.0f;           // 1.5 * 2^23
    float t = fmaf(x, 1.4426950408889634f, MAGIC);
    int   n = __float_as_int(t) - 0x4B400000;
    float f = fmaf(x, 1.4426950408889634f, -(t - MAGIC));
    float p = 1.3333558146e-3f;
    p = fmaf(p, f, 9.6181291076e-3f);
    p = fmaf(p, f, 5.5504108664e-2f);
    p = fmaf(p, f, 2.4022650696e-1f);
    p = fmaf(p, f, 6.9314718056e-1f);
    p = fmaf(p, f, 1.0f);
    return __int_as_float(__float_as_int(p) + (n << 23));
}

// --- sH: fused pair pass: atomicOr dedupe + verdict + smem segmin + smem count ---
__global__ void __launch_bounds__(1024, 2)
k_pairs(const int* __restrict__ pid, const int* __restrict__ nid) {
    __shared__ int s_min[NPROP];
    __shared__ int s_cnt[NPROP];
    int tid = threadIdx.x;
    if (tid < NPROP) { s_min[tid] = 0x7FFFFFFF; s_cnt[tid] = 0; }
    __syncthreads();

    int stride = gridDim.x * blockDim.x;
    for (int m = blockIdx.x * blockDim.x + tid; m < NPAIR; m += stride) {
        int p = pid[m];
        int n = nid[m];
        atomicMin(&s_min[p], n);
        size_t bit = (size_t)p * NPTS + n;
        unsigned int msk = 1u << (bit & 31u);
        unsigned int old = atomicOr(&g_bits[bit >> 5], msk);
        unsigned char fst = (old & msk) ? 0 : 1;
        g_first[m] = fst;
        if (fst) atomicAdd(&s_cnt[p], 1);
    }
    __syncthreads();
    if (tid < NPROP) {
        if (s_min[tid] != 0x7FFFFFFF) atomicMin(&g_rep_p[tid * PAD], s_min[tid]);
        if (s_cnt[tid]) atomicAdd(&g_count_p[tid * PAD], s_cnt[tid]);
    }
}

// --- sH: mask expansion (warp-coalesced 512B stores) ---
__global__ void k_masks(float* __restrict__ out_masks) {
    int tid = threadIdx.x;
    int t = blockIdx.x * blockDim.x + tid;   // word index (exact grid)
    int lane = tid & 31;
    int p = t / WPP;
    unsigned int w = g_bits[t];
    if (g_count_p[p * PAD] <= THRESH) w = 0u;

    size_t warp_word0 = (size_t)(t - lane);
    float4* dst = (float4*)out_masks + warp_word0 * 8;   // 8 float4 per word
    int nib = (lane & 7) * 4;
#pragma unroll
    for (int i = 0; i < 8; i++) {
        unsigned int src = __shfl_sync(0xFFFFFFFFu, w, i * 4 + (lane >> 3));
        float4 f;
        f.x = (float)((src >> (nib + 0)) & 1u);
        f.y = (float)((src >> (nib + 1)) & 1u);
        f.z = (float)((src >> (nib + 2)) & 1u);
        f.w = (float)((src >> (nib + 3)) & 1u);
        dst[(size_t)i * 32 + lane] = f;
    }
}

// --- sB: staged softmax + argmax (padded smem rows, FMA exp) ---
__global__ void k_softmax(const float* __restrict__ logit,
                          float* __restrict__ probs_out) {
    __shared__ float s[256 * 21];   // 21 KB
    int tid  = threadIdx.x;
    int base = blockIdx.x * 256;
    int count = NPTS - base;
    if (count > 256) count = 256;
    int tot = count * NCLS;

    const float* src = logit + (size_t)base * NCLS;
    for (int i = tid; i < tot; i += 256) {
        int row = i / NCLS, col = i - row * NCLS;
        s[row * 21 + col] = src[i];
    }
    __syncthreads();

    if (tid < count) {
        float* row = s + tid * 21;
        float v[NCLS];
#pragma unroll
        for (int i = 0; i < NCLS; i++) v[i] = row[i];
        float m = v[0]; int am = 0;
#pragma unroll
        for (int i = 1; i < NCLS; i++) if (v[i] > m) { m = v[i]; am = i; }
        float e[NCLS]; float sum = 0.0f;
#pragma unroll
        for (int i = 0; i < NCLS; i++) { e[i] = fexp(v[i] - m); sum += e[i]; }
        float inv = 1.0f / sum;
#pragma unroll
        for (int i = 0; i < NCLS; i++) row[i] = e[i] * inv;
        g_segpred[base + tid] = am;
    }
    __syncthreads();

    float* dst = probs_out + (size_t)base * NCLS;
    for (int i = tid; i < tot; i += 256) {
        int row = i / NCLS, col = i - row * NCLS;
        dst[i] = s[row * 21 + col];
    }
}

// --- sB: score gather for unique pairs only (runs under k_masks) ---
__global__ void __launch_bounds__(1024, 2)
k_gather(const int* __restrict__ pid, const int* __restrict__ nid,
         const float* __restrict__ probs) {
    __shared__ int   s_inst[NPROP];
    __shared__ float s_scr[NPROP];
    int tid = threadIdx.x;
    if (tid < NPROP) {
        int r = g_rep_p[tid * PAD];
        if (r > NPTS - 1) r = NPTS - 1;
        s_inst[tid] = g_segpred[r];
        s_scr[tid] = 0.0f;
    }
    __syncthreads();

    int stride = gridDim.x * blockDim.x;
    for (int m = blockIdx.x * blockDim.x + tid; m < NPAIR; m += stride) {
        if (g_first[m]) {
            int p = pid[m];
            int n = nid[m];
            atomicAdd(&s_scr[p], __ldg(&probs[(size_t)n * NCLS + s_inst[p]]));
        }
    }
    __syncthreads();
    if (tid < NPROP && s_scr[tid] != 0.0f)
        atomicAdd(&g_score_p[tid * PAD], s_scr[tid]);
}

// --- sB tail: scores + classes (tiny) ---
__global__ void k_finalize(float* __restrict__ out_scores,
                           float* __restrict__ out_classes) {
    int p = threadIdx.x;
    int c = g_count_p[p * PAD];
    int flag = (c > THRESH) ? 1 : 0;
    int cm = c > 1 ? c : 1;
    int r = g_rep_p[p * PAD];
    if (r > NPTS - 1) r = NPTS - 1;
    int inst = g_segpred[r];
    out_scores[p]  = flag ? (g_score_p[p * PAD] / (float)cm) : 0.0f;
    out_classes[p] = flag ? (float)inst : -1.0f;
}

// --- sD: bias passthrough (independent) ---
__global__ void k_bias(const float* __restrict__ bias, float* __restrict__ bias_out) {
    int t = blockIdx.x * blockDim.x + threadIdx.x;
    if (t < NPTS * 3 / 4) ((float4*)bias_out)[t] = ((const float4*)bias)[t];
}

extern "C" void kernel_launch(void* const* d_in, const int* in_sizes, int n_in,
                              void* d_out, int out_size) {
    const float* logit = (const float*)d_in[0];
    const float* bias  = (const float*)d_in[1];
    // d_in[2] = coord: dead
    const int* pid = (const int*)d_in[3];
    const int* nid = (const int*)d_in[4];

    float* out = (float*)d_out;
    float* out_scores  = out + OFF_SCORES;
    float* out_masks   = out + OFF_MASKS;
    float* out_classes = out + OFF_CLASSES;
    float* out_bias    = out + OFF_BIAS;
    float* out_probs   = out + OFF_PROBS;

    static cudaStream_t sH = nullptr, sB = nullptr, sD = nullptr;
    static cudaEvent_t eRoot, eP, eH, eB, eD;
    static void *a_bits = nullptr, *a_rep = nullptr, *a_cnt = nullptr, *a_scr = nullptr;
    if (!sH) {
        int loPri, hiPri;
        cudaDeviceGetStreamPriorityRange(&loPri, &hiPri);
        cudaStreamCreateWithPriority(&sH, cudaStreamNonBlocking, hiPri);
        cudaStreamCreateWithPriority(&sB, cudaStreamNonBlocking, loPri);
        cudaStreamCreateWithPriority(&sD, cudaStreamNonBlocking, loPri);
        cudaEventCreateWithFlags(&eRoot, cudaEventDisableTiming);
        cudaEventCreateWithFlags(&eP, cudaEventDisableTiming);
        cudaEventCreateWithFlags(&eH, cudaEventDisableTiming);
        cudaEventCreateWithFlags(&eB, cudaEventDisableTiming);
        cudaEventCreateWithFlags(&eD, cudaEventDisableTiming);
        cudaGetSymbolAddress(&a_bits, g_bits);
        cudaGetSymbolAddress(&a_rep,  g_rep_p);
        cudaGetSymbolAddress(&a_cnt,  g_count_p);
        cudaGetSymbolAddress(&a_scr,  g_score_p);
    }

    // fork from stream 0
    cudaEventRecord(eRoot, 0);
    cudaStreamWaitEvent(sH, eRoot, 0);
    cudaStreamWaitEvent(sB, eRoot, 0);
    cudaStreamWaitEvent(sD, eRoot, 0);

    // sH (critical, high priority): memsets -> pairs(Or+min+count) -> masks
    cudaMemsetAsync(a_bits, 0, WORDS * 4, sH);
    cudaMemsetAsync(a_cnt, 0, NPROP * PAD * 4, sH);
    cudaMemsetAsync(a_rep, 0x7F, NPROP * PAD * 4, sH);   // 0x7F7F7F7F > NPTS
    k_pairs<<<296, 1024, 0, sH>>>(pid, nid);
    cudaEventRecord(eP, sH);
    k_masks<<<(int)(WORDS / 256), 256, 0, sH>>>(out_masks);
    cudaEventRecord(eH, sH);

    // sB (low priority): softmax -> (wait pairs) gather -> finalize
    cudaMemsetAsync(a_scr, 0, NPROP * PAD * 4, sB);
    k_softmax<<<(NPTS + 255) / 256, 256, 0, sB>>>(logit, out_probs);
    cudaStreamWaitEvent(sB, eP, 0);
    k_gather<<<296, 1024, 0, sB>>>(pid, nid, out_probs);
    k_finalize<<<1, NPROP, 0, sB>>>(out_scores, out_classes);
    cudaEventRecord(eB, sB);

    // sD (low priority): bias passthrough
    k_bias<<<(NPTS * 3 / 4 + 255) / 256, 256, 0, sD>>>(bias, out_bias);
    cudaEventRecord(eD, sD);

    // join everything into stream 0
    cudaStreamWaitEvent(0, eH, 0);
    cudaStreamWaitEvent(0, eB, 0);
    cudaStreamWaitEvent(0, eD, 0);
}